// round 12
// baseline (speedup 1.0000x reference)
#include <cuda_runtime.h>
#include <cuda_bf16.h>
#include <cuda_fp16.h>
#include <math.h>
#include <stdint.h>

#define HH 256
#define WW 256
#define HWSZ 65536
#define BB 2
#define C64 64
#define C128 128
#define C256 256

#define SW128(off) ((off) ^ (((off) >> 3) & 0x70))

__device__ __forceinline__ uint32_t smem_u32(const void* p) {
    uint32_t a;
    asm("{ .reg .u64 t; cvta.to.shared.u64 t, %1; cvt.u32.u64 %0, t; }" : "=r"(a) : "l"(p));
    return a;
}
__device__ __forceinline__ void cpa16(uint32_t dst, const void* src, int sz) {
    asm volatile("cp.async.cg.shared.global [%0], [%1], 16, %2;"
                 :: "r"(dst), "l"(src), "r"(sz) : "memory");
}
__device__ __forceinline__ void cpa_commit() {
    asm volatile("cp.async.commit_group;" ::: "memory");
}
template<int N>
__device__ __forceinline__ void cpa_wait() {
    asm volatile("cp.async.wait_group %0;" :: "n"(N) : "memory");
}
__device__ __forceinline__ void ldm_x4(uint32_t& r0, uint32_t& r1, uint32_t& r2, uint32_t& r3,
                                       uint32_t addr) {
    asm volatile("ldmatrix.sync.aligned.m8n8.x4.shared.b16 {%0,%1,%2,%3}, [%4];"
                 : "=r"(r0), "=r"(r1), "=r"(r2), "=r"(r3) : "r"(addr));
}
__device__ __forceinline__ void mma_bf16(float* c, const uint32_t* a, uint32_t b0, uint32_t b1) {
    asm volatile("mma.sync.aligned.m16n8k16.row.col.f32.bf16.bf16.f32 "
                 "{%0,%1,%2,%3}, {%4,%5,%6,%7}, {%8,%9}, {%0,%1,%2,%3};"
                 : "+f"(c[0]), "+f"(c[1]), "+f"(c[2]), "+f"(c[3])
                 : "r"(a[0]), "r"(a[1]), "r"(a[2]), "r"(a[3]), "r"(b0), "r"(b1));
}
__device__ __forceinline__ void mma_f16(float* c, const uint32_t* a, uint32_t b0, uint32_t b1) {
    asm volatile("mma.sync.aligned.m16n8k16.row.col.f32.f16.f16.f32 "
                 "{%0,%1,%2,%3}, {%4,%5,%6,%7}, {%8,%9}, {%0,%1,%2,%3};"
                 : "+f"(c[0]), "+f"(c[1]), "+f"(c[2]), "+f"(c[3])
                 : "r"(a[0]), "r"(a[1]), "r"(a[2]), "r"(a[3]), "r"(b0), "r"(b1));
}

// ================= scratch (device globals) =================
__device__ float g_up   [BB * C64 * HWSZ];
__device__ float g_h1raw[BB * HWSZ * C64];
__device__ float g_b2   [BB * C64 * HWSZ];
__device__ float g_red[256];
__device__ float g_ab1[128];
__device__ float g_ab2[128];
__device__ __nv_bfloat16 g_x1_h[BB * 16384 * C64];
__device__ __nv_bfloat16 g_x1_l[BB * 16384 * C64];
__device__ __nv_bfloat16 g_wu_h[C256 * 64];
__device__ __nv_bfloat16 g_wu_l[C256 * 64];
__device__ __half g_cat [BB * HWSZ * C128];
__device__ __half g_xd  [BB * HWSZ * C128];
__device__ __half g_wo  [18 * C256 * 64];
__device__ __half g_w1  [18 * C64 * 64];
__device__ __half g_w2  [9 * C64 * 64];

// ================= combined prep: all weights + zero stats =================
__global__ void prep_all_k(const float* __restrict__ offw, const float* __restrict__ c1w,
                           const float* __restrict__ c2w, const float* __restrict__ upw,
                           __half* __restrict__ wo, __half* __restrict__ w1,
                           __half* __restrict__ w2,
                           __nv_bfloat16* __restrict__ wuh, __nv_bfloat16* __restrict__ wul,
                           float* __restrict__ red)
{
    int i = blockIdx.x * 256 + threadIdx.x;
    if (i < 256) red[i] = 0.f;
    if (i < 294912) {                    // offconv weights: N=256, CIN=128
        int t  = i % 9;
        int ci = (i / 9) % 128;
        int o  = i / (9 * 128);
        int q = ci >> 6, cc = ci & 63;
        int kc = t * 2 + q;
        wo[(kc * 256 + o) * 64 + cc] = __float2half_rn(offw[i]);
    } else if (i < 294912 + 73728) {     // conv1: N=64, CIN=128
        int j = i - 294912;
        int t  = j % 9;
        int ci = (j / 9) % 128;
        int o  = j / (9 * 128);
        int q = ci >> 6, cc = ci & 63;
        int kc = t * 2 + q;
        w1[(kc * 64 + o) * 64 + cc] = __float2half_rn(c1w[j]);
    } else if (i < 294912 + 73728 + 36864) {  // conv2: N=64, CIN=64
        int j = i - 294912 - 73728;
        int t  = j % 9;
        int ci = (j / 9) % 64;
        int o  = j / (9 * 64);
        int kc = t;
        w2[(kc * 64 + o) * 64 + (ci & 63)] = __float2half_rn(c2w[j]);
    } else if (i < 294912 + 73728 + 36864 + 16384) {  // upconv: bf16 hi/lo
        int s = i - 294912 - 73728 - 36864;
        int n = s & 255;
        int cc = s >> 8;
        float v = upw[s];
        __nv_bfloat16 h = __float2bfloat16(v);
        float lo = v - __bfloat162float(h);
        wuh[n * 64 + cc] = h;
        wul[n * 64 + cc] = __float2bfloat16(lo);
    }
}

// ================= x1 NCHW -> NHWC bf16 hi/lo =================
__global__ void __launch_bounds__(256)
tc_x1_k(const float* __restrict__ in0,
        __nv_bfloat16* __restrict__ oh, __nv_bfloat16* __restrict__ ol)
{
    __shared__ float s[64][33];
    const int s0 = blockIdx.x * 32;
    const int b = blockIdx.y;
    const int tid = threadIdx.x;
    const int px = tid & 31;
#pragma unroll 4
    for (int c = tid >> 5; c < 64; c += 8)
        s[c][px] = in0[(b * 64 + c) * 16384 + s0 + px];
    __syncthreads();
#pragma unroll 4
    for (int e = tid; e < 32 * 64; e += 256) {
        int p = e >> 6, c = e & 63;
        float v = s[c][p];
        __nv_bfloat16 h = __float2bfloat16(v);
        float lo = v - __bfloat162float(h);
        size_t idx = ((size_t)(b * 16384 + s0 + p)) * 64 + c;
        oh[idx] = h;
        ol[idx] = __float2bfloat16(lo);
    }
}

// ================= concat -> NHWC fp16 =================
__global__ void __launch_bounds__(256)
tc_cat_k(const float* __restrict__ x2, const float* __restrict__ up,
         __half* __restrict__ oc)
{
    __shared__ float s[128][33];
    const int s0 = blockIdx.x * 32;
    const int b = blockIdx.y;
    const int tid = threadIdx.x;
    const int px = tid & 31;
#pragma unroll 4
    for (int c = tid >> 5; c < 128; c += 8) {
        const float* src = (c < 64) ? x2 + (b * 64 + c) * HWSZ
                                    : up + (b * 64 + (c - 64)) * HWSZ;
        s[c][px] = src[s0 + px];
    }
    __syncthreads();
#pragma unroll 4
    for (int e = tid; e < 32 * 128; e += 256) {
        int p = e >> 7, c = e & 127;
        size_t idx = ((size_t)(b * HWSZ + s0 + p)) * 128 + c;
        oc[idx] = __float2half_rn(s[c][p]);
    }
}

// ================= upconv via mma (bf16x3) =================
__global__ void __launch_bounds__(256, 2)
upmma_k(const __nv_bfloat16* __restrict__ ah_g, const __nv_bfloat16* __restrict__ al_g,
        const __nv_bfloat16* __restrict__ bh_g, const __nv_bfloat16* __restrict__ bl_g,
        const float* __restrict__ upb, float* __restrict__ up)
{
    extern __shared__ char dsm[];
    constexpr int A_H = 0, A_L = 16384, B_H = 32768, B_L = 40960;
    uint32_t raw = smem_u32(dsm);
    uint32_t base = (raw + 1023u) & ~1023u;
    char* smc = dsm + (base - raw);
    const int tid = threadIdx.x;
    const int wid = tid >> 5;
    const int lane = tid & 31;

    const int p0 = blockIdx.x * 128;
    const int b  = p0 >> 14;
    const int sb = p0 & 16383;
    const int y0 = sb >> 7;
    const int oc0 = blockIdx.y * 64;

#pragma unroll
    for (int it = 0; it < 4; it++) {
        int idx = it * 256 + tid;
        int m = idx >> 3, ch = idx & 7;
        size_t gi = ((size_t)(p0 + m)) * 64 + ch * 8;
        uint32_t sw = SW128(m * 128 + ch * 16);
        cpa16(base + A_H + sw, ah_g + gi, 16);
        cpa16(base + A_L + sw, al_g + gi, 16);
    }
#pragma unroll
    for (int it = 0; it < 2; it++) {
        int idx = it * 256 + tid;
        int o = idx >> 3, ch = idx & 7;
        size_t gi = ((size_t)(oc0 + o)) * 64 + ch * 8;
        uint32_t sw = SW128(o * 128 + ch * 16);
        cpa16(base + B_H + sw, bh_g + gi, 16);
        cpa16(base + B_L + sw, bl_g + gi, 16);
    }
    cpa_commit();
    cpa_wait<0>();
    __syncthreads();

    float acc[8][4];
#pragma unroll
    for (int g = 0; g < 8; g++)
#pragma unroll
        for (int j = 0; j < 4; j++) acc[g][j] = 0.f;

    const uint32_t Ah = base + A_H, Al = base + A_L;
    const uint32_t Bh = base + B_H, Bl = base + B_L;
    const int arow = wid * 16 + (lane & 15);
    const int nrow = lane & 15;
    const int chalf = (lane >> 4) * 16;
#pragma unroll
    for (int kk = 0; kk < 4; kk++) {
        const int cb = chalf + kk * 32;
        uint32_t ah[4], al[4];
        ldm_x4(ah[0], ah[1], ah[2], ah[3], Ah + SW128(arow * 128 + cb));
        ldm_x4(al[0], al[1], al[2], al[3], Al + SW128(arow * 128 + cb));
#pragma unroll
        for (int g = 0; g < 4; g++) {
            uint32_t off = SW128((g * 16 + nrow) * 128 + cb);
            uint32_t t0, t1, t2, t3, u0, u1, u2, u3;
            ldm_x4(t0, t1, t2, t3, Bh + off);
            ldm_x4(u0, u1, u2, u3, Bl + off);
            mma_bf16(acc[2 * g],     ah, t0, t2);
            mma_bf16(acc[2 * g + 1], ah, t1, t3);
            mma_bf16(acc[2 * g],     al, t0, t2);
            mma_bf16(acc[2 * g + 1], al, t1, t3);
            mma_bf16(acc[2 * g],     ah, u0, u2);
            mma_bf16(acc[2 * g + 1], ah, u1, u3);
        }
    }
    __syncthreads();

    float* sepi = (float*)smc;
    const int em = wid * 16 + (lane >> 2);
    const int en = (lane & 3) * 2;
#pragma unroll
    for (int g = 0; g < 8; g++) {
        int n0 = g * 8 + en;
        sepi[n0 * 132 + em]           = acc[g][0];
        sepi[(n0 + 1) * 132 + em]     = acc[g][1];
        sepi[n0 * 132 + em + 8]       = acc[g][2];
        sepi[(n0 + 1) * 132 + em + 8] = acc[g][3];
    }
    __syncthreads();
#pragma unroll 4
    for (int j = 0; j < 32; j++) {
        int lin = j * 256 + tid;
        int n = lin >> 7, m = lin & 127;
        int ng = oc0 + n;
        int o = ng >> 2, k = (ng >> 1) & 1, l = ng & 1;
        float v = sepi[n * 132 + m] + upb[o];
        up[((size_t)(b * 64 + o) << 16) + (2 * y0 + k) * 256 + 2 * m + l] = v;
    }
}

// ============ ROW-STAGED implicit-GEMM 3x3 conv (generalized) ============
// EPI 0: NCHW fp32 + bias + stats. EPI 1: NHWC fp32 + bias + stats.
// EPI 3: fused deformable gather (offconv) -> xd NHWC fp16, coalesced.
// AFF=1 (CINQ==1): fp32 NHWC input with affine+relu+fp16 on stage.
template<int NTOT, int CINQ, int NT, int EPI, int AFF>
__global__ void __launch_bounds__(512)
convrs_k(const void* __restrict__ a_gv,
         const __half* __restrict__ bh_g,
         const float* __restrict__ aff,
         const float* __restrict__ bias, void* __restrict__ outv,
         float* __restrict__ red,
         const float* __restrict__ x2, const float* __restrict__ up,
         __half* __restrict__ xd)
{
    extern __shared__ char dsm[];
    constexpr int CCH = CINQ * 64;
    constexpr int NW  = NT / 2;
    constexpr int NG  = NW / 16;
    constexpr int A_BYTES = 776 * 128;
    constexpr int B_OFF = A_BYTES;              // 99328
    constexpr int B_BUF = NT * 128;

    uint32_t raw = smem_u32(dsm);
    uint32_t base = (raw + 1023u) & ~1023u;
    char* smc = dsm + (base - raw);
    const int tid = threadIdx.x;
    const int wid = tid >> 5;
    const int lane = tid & 31;
    const int mw = wid & 7;
    const int nw = wid >> 3;

    const int b  = blockIdx.x >> 8;
    const int y0 = blockIdx.x & 255;
    const int sb = y0 << 8;
    const int oc0 = blockIdx.y * NT;

    auto stageA = [&](int q) {
        if (AFF) {
            const float* a32 = (const float*)a_gv;
            for (int idx = tid; idx < 6192; idx += 512) {
                int p = idx >> 3, ch = idx & 7;
                int brow = p / 258;
                int bcol = p - brow * 258;
                int gy = y0 + brow - 1;
                int gx = bcol - 1;
                bool inb = ((unsigned)gy < 256u) && ((unsigned)gx < 256u);
                uint4 pk = make_uint4(0, 0, 0, 0);
                if (inb) {
                    size_t gi = (((size_t)b << 16) + (gy << 8) + gx) * 64 + ch * 8;
                    float4 v0 = *(const float4*)(a32 + gi);
                    float4 v1 = *(const float4*)(a32 + gi + 4);
                    float vv[8] = {v0.x, v0.y, v0.z, v0.w, v1.x, v1.y, v1.z, v1.w};
                    unsigned short hs[8];
#pragma unroll
                    for (int j = 0; j < 8; j++) {
                        int c = ch * 8 + j;
                        float y = fmaxf(fmaf(vv[j], __ldg(aff + c), __ldg(aff + 64 + c)), 0.f);
                        __half hb = __float2half_rn(y);
                        hs[j] = *(unsigned short*)&hb;
                    }
                    pk = *(uint4*)hs;
                }
                *(uint4*)(smc + SW128(p * 128 + ch * 16)) = pk;
            }
        } else {
            const __half* a_g = (const __half*)a_gv;
            for (int idx = tid; idx < 6192; idx += 512) {
                int p = idx >> 3, ch = idx & 7;
                int brow = p / 258;
                int bcol = p - brow * 258;
                int gy = y0 + brow - 1;
                int gx = bcol - 1;
                bool inb = ((unsigned)gy < 256u) && ((unsigned)gx < 256u);
                size_t gi = (((size_t)b << 16) + (gy << 8) + gx) * CCH + q * 64 + ch * 8;
                if (!inb) gi = 0;
                cpa16(base + SW128(p * 128 + ch * 16), a_g + gi, inb ? 16 : 0);
            }
        }
    };
    auto stageB = [&](int kc, int buf) {
        const uint32_t bbase = base + B_OFF + buf * B_BUF;
        for (int idx = tid; idx < NT * 8; idx += 512) {
            int o = idx >> 3, ch = idx & 7;
            size_t gi = ((size_t)kc * NTOT + oc0 + o) * 64 + ch * 8;
            cpa16(bbase + SW128(o * 128 + ch * 16), bh_g + gi, 16);
        }
    };

    float acc[2][NW / 8][4];
#pragma unroll
    for (int ms = 0; ms < 2; ms++)
#pragma unroll
        for (int g = 0; g < NW / 8; g++)
#pragma unroll
            for (int j = 0; j < 4; j++) acc[ms][g][j] = 0.f;

    stageA(0);
    stageB(0, 0);
    cpa_commit();

    const int chalf = (lane >> 4) * 16;
    const int nrow = lane & 15;
    const int arowb = mw * 32 + (lane & 15);

#pragma unroll 1
    for (int q = 0; q < CINQ; q++) {
#pragma unroll 1
        for (int t = 0; t < 9; t++) {
            const int s = q * 9 + t;
            if (t < 8) {
                stageB((t + 1) * CINQ + q, (s + 1) & 1);
                cpa_commit();
                cpa_wait<1>();
            } else {
                cpa_wait<0>();
            }
            __syncthreads();

            const int ky = t / 3 - 1;
            const int kx = t % 3 - 1;
            const uint32_t Bb = base + B_OFF + (s & 1) * B_BUF;
            const int rb = (ky + 1) * 258 + kx + 1 + arowb;

#pragma unroll
            for (int kk = 0; kk < 4; kk++) {
                const int cb = chalf + kk * 32;
                uint32_t ah[2][4];
#pragma unroll
                for (int ms = 0; ms < 2; ms++) {
                    int r = rb + ms * 16;
                    ldm_x4(ah[ms][0], ah[ms][1], ah[ms][2], ah[ms][3],
                           base + SW128(r * 128 + cb));
                }
#pragma unroll
                for (int g = 0; g < NG; g++) {
                    uint32_t off = SW128((nw * NW + g * 16 + nrow) * 128 + cb);
                    uint32_t t0, t1, t2, t3;
                    ldm_x4(t0, t1, t2, t3, Bb + off);
#pragma unroll
                    for (int ms = 0; ms < 2; ms++) {
                        mma_f16(acc[ms][2 * g],     ah[ms], t0, t2);
                        mma_f16(acc[ms][2 * g + 1], ah[ms], t1, t3);
                    }
                }
            }
            __syncthreads();

            if (t == 8 && q + 1 < CINQ) {
                stageA(q + 1);
                stageB(q + 1, (s + 1) & 1);
                cpa_commit();
            }
        }
    }

    // ---- stage [n][m=256] fp32 in smem (pitch 260) ----
    float* sepi = (float*)smc;
    const int em = mw * 32 + (lane >> 2);
    const int ecol = (lane & 3) * 2;
#pragma unroll
    for (int ms = 0; ms < 2; ms++) {
        int m = em + ms * 16;
#pragma unroll
        for (int g = 0; g < NG; g++) {
            int nb = nw * NW + g * 16 + ecol;
            sepi[nb * 260 + m]           = acc[ms][2 * g][0];
            sepi[(nb + 1) * 260 + m]     = acc[ms][2 * g][1];
            sepi[nb * 260 + m + 8]       = acc[ms][2 * g][2];
            sepi[(nb + 1) * 260 + m + 8] = acc[ms][2 * g][3];
            int nb2 = nb + 8;
            sepi[nb2 * 260 + m]           = acc[ms][2 * g + 1][0];
            sepi[(nb2 + 1) * 260 + m]     = acc[ms][2 * g + 1][1];
            sepi[nb2 * 260 + m + 8]       = acc[ms][2 * g + 1][2];
            sepi[(nb2 + 1) * 260 + m + 8] = acc[ms][2 * g + 1][3];
        }
    }
    __syncthreads();

    if (EPI == 0) {
        float* out = (float*)outv;
#pragma unroll
        for (int j = 0; j < NT / 8; j++) {
            int lin = j * 512 + tid;
            int n = lin >> 6;
            int seg = lin & 63;
            float4 v = *(float4*)(sepi + n * 260 + seg * 4);
            float bz = bias ? bias[oc0 + n] : 0.f;
            v.x += bz; v.y += bz; v.z += bz; v.w += bz;
            *(float4*)(out + (((size_t)(b * NTOT + oc0 + n)) << 16) + sb + seg * 4) = v;
        }
    } else if (EPI == 1) {
        float* out = (float*)outv;
#pragma unroll
        for (int j = 0; j < 8; j++) {
            int lin = j * 512 + tid;
            int m = lin >> 4;
            int cq = lin & 15;
            float4 v;
            v.x = sepi[(cq * 4 + 0) * 260 + m] + bias[cq * 4 + 0];
            v.y = sepi[(cq * 4 + 1) * 260 + m] + bias[cq * 4 + 1];
            v.z = sepi[(cq * 4 + 2) * 260 + m] + bias[cq * 4 + 2];
            v.w = sepi[(cq * 4 + 3) * 260 + m] + bias[cq * 4 + 3];
            *(float4*)(out + ((size_t)(b * 65536 + sb + m)) * 64 + cq * 4) = v;
        }
    } else {
        // ---- fused deformable gather (NT==128) ----
        // Mapping per CTA: q = oc0+ql, c = q>>1, task pair m=(2e,2e+1);
        // h = (q&1)*128 + (y0>>1), w = (y0&1)*128 + e  (constant h, contiguous w).
        __half* sval = (__half*)(smc + 133632);      // [128 e][72 pitch] halves
        const int hbase = y0 >> 1;
        const int wbase = (y0 & 1) << 7;
        const int c0 = oc0 >> 1;
#pragma unroll 1
        for (int par = 0; par < 2; par++) {
#pragma unroll 1
            for (int it = 0; it < 16; it++) {
                int idx = it * 512 + tid;            // 0..8191
                int e = idx >> 6;                    // 0..127
                int j = idx & 63;                    // 0..63
                int ql = 2 * j + par;
                float oy = sepi[ql * 260 + 2 * e];
                float ox = sepi[ql * 260 + 2 * e + 1];
                int c = c0 + j;
                int h = par * 128 + hbase;
                int w = wbase + e;
                const float* src = (c < 64) ? x2 + ((size_t)(b * 64 + c) << 16)
                                            : up + ((size_t)(b * 64 + c - 64) << 16);
                float cy = fminf(fmaxf(oy + (float)h, 0.f), 255.f);
                float cx = fminf(fmaxf(ox + (float)w, 0.f), 255.f);
                float y0f = floorf(cy), x0f = floorf(cx);
                int iy0 = (int)y0f;
                int ix0 = (int)x0f;
                int iy1 = (int)ceilf(cy);
                int ix1 = (int)ceilf(cx);
                float v00 = src[iy0 * 256 + ix0];
                float v10 = src[iy1 * 256 + ix0];
                float v01 = src[iy0 * 256 + ix1];
                float v11 = src[iy1 * 256 + ix1];
                float wy = cy - y0f, wx = cx - x0f;
                float vt = v00 + (v10 - v00) * wy;
                float vb = v01 + (v11 - v01) * wy;
                sval[e * 72 + j] = __float2half_rn(vt + (vb - vt) * wx);
            }
            __syncthreads();
            // coalesced writes: 128 pixels x 64 ch (16 ch per thread)
            {
                int e = tid >> 2;
                int qd = tid & 3;
                int h = par * 128 + hbase;
                int w = wbase + e;
                size_t og = ((size_t)(b * 65536 + h * 256 + w)) * 128 + c0 + qd * 16;
                const uint4* sp = (const uint4*)(sval + e * 72 + qd * 16);
                uint4* dp = (uint4*)((unsigned short*)xd + og);
                dp[0] = sp[0];
                dp[1] = sp[1];
            }
            __syncthreads();
        }
    }

    if ((EPI == 0 || EPI == 1) && red) {
        float* sred = sepi + NT * 260;
        int n = tid >> 3, part = tid & 7;
        float bz = bias ? bias[oc0 + n] : 0.f;
        float s1 = 0.f, s2 = 0.f;
        const float* rowp = sepi + n * 260 + part * 32;
#pragma unroll
        for (int j = 0; j < 32; j++) {
            float v = rowp[j] + bz;
            s1 += v;
            s2 = fmaf(v, v, s2);
        }
        sred[(0 * 64 + n) * 8 + part] = s1;
        sred[(1 * 64 + n) * 8 + part] = s2;
        __syncthreads();
        if (tid < 128) {
            int which = tid >> 6, n2 = tid & 63;
            const float* pr = sred + (which * 64 + n2) * 8;
            float s = 0.f;
#pragma unroll
            for (int j = 0; j < 8; j++) s += pr[j];
            atomicAdd(red + which * 64 + oc0 + n2, s);
        }
    }
}

// ================= small kernels =================
__global__ void bnfin_k(const float* __restrict__ red,
                        const float* __restrict__ gamma, const float* __restrict__ beta,
                        float* __restrict__ ab)
{
    int c = threadIdx.x;
    const float invn = 1.f / 131072.f;
    float m = red[c] * invn;
    float var = fmaf(-m, m, red[64 + c] * invn);
    float a = gamma[c] * rsqrtf(var + 1e-5f);
    ab[c] = a;
    ab[64 + c] = fmaf(-m, a, beta[c]);
}

__global__ void __launch_bounds__(256)
bnrelu_out_k(const float* __restrict__ buf, const float* __restrict__ ab,
             float* __restrict__ out)
{
    int i4 = blockIdx.x * 256 + threadIdx.x;
    int c = (i4 >> 14) & 63;
    float a = __ldg(ab + c), bz = __ldg(ab + 64 + c);
    float4 v = *(const float4*)(buf + (size_t)i4 * 4);
    v.x = fmaxf(fmaf(v.x, a, bz), 0.f);
    v.y = fmaxf(fmaf(v.y, a, bz), 0.f);
    v.z = fmaxf(fmaf(v.z, a, bz), 0.f);
    v.w = fmaxf(fmaf(v.w, a, bz), 0.f);
    *(float4*)(out + (size_t)i4 * 4) = v;
}

// ================= launch =================
extern "C" void kernel_launch(void* const* d_in, const int* in_sizes, int n_in,
                              void* d_out, int out_size)
{
    const float* x1   = (const float*)d_in[0];
    const float* x2   = (const float*)d_in[1];
    const float* up_w = (const float*)d_in[2];
    const float* up_b = (const float*)d_in[3];
    const float* offw = (const float*)d_in[4];
    const float* c1w  = (const float*)d_in[5];
    const float* c1b  = (const float*)d_in[6];
    const float* g1   = (const float*)d_in[7];
    const float* b1   = (const float*)d_in[8];
    const float* c2w  = (const float*)d_in[9];
    const float* c2b  = (const float*)d_in[10];
    const float* g2   = (const float*)d_in[11];
    const float* b2   = (const float*)d_in[12];
    float* outp = (float*)d_out;

    float *p_up, *p_h1raw, *p_b2, *p_red, *p_ab1, *p_ab2;
    cudaGetSymbolAddress((void**)&p_up,    g_up);
    cudaGetSymbolAddress((void**)&p_h1raw, g_h1raw);
    cudaGetSymbolAddress((void**)&p_b2,    g_b2);
    cudaGetSymbolAddress((void**)&p_red,   g_red);
    cudaGetSymbolAddress((void**)&p_ab1,   g_ab1);
    cudaGetSymbolAddress((void**)&p_ab2,   g_ab2);
    __nv_bfloat16 *p_x1_h, *p_x1_l, *p_wu_h, *p_wu_l;
    cudaGetSymbolAddress((void**)&p_x1_h, g_x1_h);
    cudaGetSymbolAddress((void**)&p_x1_l, g_x1_l);
    cudaGetSymbolAddress((void**)&p_wu_h, g_wu_h);
    cudaGetSymbolAddress((void**)&p_wu_l, g_wu_l);
    __half *p_cat, *p_xd, *p_wo, *p_w1, *p_w2;
    cudaGetSymbolAddress((void**)&p_cat, g_cat);
    cudaGetSymbolAddress((void**)&p_xd,  g_xd);
    cudaGetSymbolAddress((void**)&p_wo,  g_wo);
    cudaGetSymbolAddress((void**)&p_w1,  g_w1);
    cudaGetSymbolAddress((void**)&p_w2,  g_w2);

    const int smem_off = 153600;   // sepi 133120 + align + sval 18432
    const int smem_c   = 135168;
    const int smem_up  = 49152 + 1024;
    cudaFuncSetAttribute(convrs_k<256, 2, 128, 3, 0>, cudaFuncAttributeMaxDynamicSharedMemorySize, smem_off);
    cudaFuncSetAttribute(convrs_k<64, 2, 64, 1, 0>,   cudaFuncAttributeMaxDynamicSharedMemorySize, smem_c);
    cudaFuncSetAttribute(convrs_k<64, 1, 64, 0, 1>,   cudaFuncAttributeMaxDynamicSharedMemorySize, smem_c);
    cudaFuncSetAttribute(upmma_k, cudaFuncAttributeMaxDynamicSharedMemorySize, smem_up);

    // 0) combined prep (all weights + zero stats)
    prep_all_k<<<1648, 256>>>(offw, c1w, c2w, up_w, p_wo, p_w1, p_w2,
                              p_wu_h, p_wu_l, p_red);

    // 1) x1 -> NHWC bf16 hi/lo, upconv via bf16x3 mma
    tc_x1_k<<<dim3(512, 2), 256>>>(x1, p_x1_h, p_x1_l);
    upmma_k<<<dim3(256, 4), 256, smem_up>>>(p_x1_h, p_x1_l, p_wu_h, p_wu_l, up_b, p_up);

    // 2) concat -> NHWC fp16
    tc_cat_k<<<dim3(2048, 2), 256>>>(x2, p_up, p_cat);

    // 3) offset conv + FUSED deformable gather -> xd NHWC fp16
    convrs_k<256, 2, 128, 3, 0><<<dim3(512, 2), 512, smem_off>>>(
        p_cat, p_wo, nullptr, nullptr, nullptr, nullptr, x2, p_up, p_xd);

    // 4) row-staged conv1 (1-pass) -> NHWC fp32 + BN1 stats
    convrs_k<64, 2, 64, 1, 0><<<dim3(512, 1), 512, smem_c>>>(
        p_xd, p_w1, nullptr, c1b, p_h1raw, p_red, nullptr, nullptr, nullptr);
    bnfin_k<<<1, 64>>>(p_red, g1, b1, p_ab1);

    // 5) row-staged conv2 (1-pass, fused BN1 affine+relu) -> NCHW fp32 + BN2 stats
    convrs_k<64, 1, 64, 0, 1><<<dim3(512, 1), 512, smem_c>>>(
        p_h1raw, p_w2, p_ab1, c2b, p_b2, p_red + 128, nullptr, nullptr, nullptr);
    bnfin_k<<<1, 64>>>(p_red + 128, g2, b2, p_ab2);

    // 6) final BN+ReLU
    bnrelu_out_k<<<8192, 256>>>(p_b2, p_ab2, outp);
}

// round 14
// speedup vs baseline: 1.2576x; 1.2576x over previous
#include <cuda_runtime.h>
#include <cuda_bf16.h>
#include <cuda_fp16.h>
#include <math.h>
#include <stdint.h>

#define HH 256
#define WW 256
#define HWSZ 65536
#define BB 2
#define C64 64
#define C128 128
#define C256 256

#define SW128(off) ((off) ^ (((off) >> 3) & 0x70))

__device__ __forceinline__ uint32_t smem_u32(const void* p) {
    uint32_t a;
    asm("{ .reg .u64 t; cvta.to.shared.u64 t, %1; cvt.u32.u64 %0, t; }" : "=r"(a) : "l"(p));
    return a;
}
__device__ __forceinline__ void cpa16(uint32_t dst, const void* src, int sz) {
    asm volatile("cp.async.cg.shared.global [%0], [%1], 16, %2;"
                 :: "r"(dst), "l"(src), "r"(sz) : "memory");
}
__device__ __forceinline__ void cpa_commit() {
    asm volatile("cp.async.commit_group;" ::: "memory");
}
template<int N>
__device__ __forceinline__ void cpa_wait() {
    asm volatile("cp.async.wait_group %0;" :: "n"(N) : "memory");
}
__device__ __forceinline__ void ldm_x4(uint32_t& r0, uint32_t& r1, uint32_t& r2, uint32_t& r3,
                                       uint32_t addr) {
    asm volatile("ldmatrix.sync.aligned.m8n8.x4.shared.b16 {%0,%1,%2,%3}, [%4];"
                 : "=r"(r0), "=r"(r1), "=r"(r2), "=r"(r3) : "r"(addr));
}
__device__ __forceinline__ void mma_bf16(float* c, const uint32_t* a, uint32_t b0, uint32_t b1) {
    asm volatile("mma.sync.aligned.m16n8k16.row.col.f32.bf16.bf16.f32 "
                 "{%0,%1,%2,%3}, {%4,%5,%6,%7}, {%8,%9}, {%0,%1,%2,%3};"
                 : "+f"(c[0]), "+f"(c[1]), "+f"(c[2]), "+f"(c[3])
                 : "r"(a[0]), "r"(a[1]), "r"(a[2]), "r"(a[3]), "r"(b0), "r"(b1));
}
__device__ __forceinline__ void mma_f16(float* c, const uint32_t* a, uint32_t b0, uint32_t b1) {
    asm volatile("mma.sync.aligned.m16n8k16.row.col.f32.f16.f16.f32 "
                 "{%0,%1,%2,%3}, {%4,%5,%6,%7}, {%8,%9}, {%0,%1,%2,%3};"
                 : "+f"(c[0]), "+f"(c[1]), "+f"(c[2]), "+f"(c[3])
                 : "r"(a[0]), "r"(a[1]), "r"(a[2]), "r"(a[3]), "r"(b0), "r"(b1));
}

// ================= scratch (device globals) =================
__device__ float g_up   [BB * C64 * HWSZ];
__device__ __half g_off [BB * C256 * HWSZ];
__device__ float g_h1raw[BB * HWSZ * C64];
__device__ float g_b2   [BB * C64 * HWSZ];
__device__ float g_red[256];
__device__ float g_ab1[128];
__device__ float g_ab2[128];
__device__ __nv_bfloat16 g_x1_h[BB * 16384 * C64];
__device__ __nv_bfloat16 g_x1_l[BB * 16384 * C64];
__device__ __nv_bfloat16 g_wu_h[C256 * 64];
__device__ __nv_bfloat16 g_wu_l[C256 * 64];
__device__ __half g_cat [BB * HWSZ * C128];
__device__ __half g_xd  [BB * HWSZ * C128];
__device__ __half g_wo  [18 * C256 * 64];
__device__ __half g_w1  [18 * C64 * 64];
__device__ __half g_w2  [9 * C64 * 64];

// ================= combined prep: all weights + zero stats =================
__global__ void prep_all_k(const float* __restrict__ offw, const float* __restrict__ c1w,
                           const float* __restrict__ c2w, const float* __restrict__ upw,
                           __half* __restrict__ wo, __half* __restrict__ w1,
                           __half* __restrict__ w2,
                           __nv_bfloat16* __restrict__ wuh, __nv_bfloat16* __restrict__ wul,
                           float* __restrict__ red)
{
    int i = blockIdx.x * 256 + threadIdx.x;
    if (i < 256) red[i] = 0.f;
    if (i < 294912) {                    // offconv weights: N=256, CIN=128
        int t  = i % 9;
        int ci = (i / 9) % 128;
        int o  = i / (9 * 128);
        int q = ci >> 6, cc = ci & 63;
        int kc = t * 2 + q;
        wo[(kc * 256 + o) * 64 + cc] = __float2half_rn(offw[i]);
    } else if (i < 294912 + 73728) {     // conv1: N=64, CIN=128
        int j = i - 294912;
        int t  = j % 9;
        int ci = (j / 9) % 128;
        int o  = j / (9 * 128);
        int q = ci >> 6, cc = ci & 63;
        int kc = t * 2 + q;
        w1[(kc * 64 + o) * 64 + cc] = __float2half_rn(c1w[j]);
    } else if (i < 294912 + 73728 + 36864) {  // conv2: N=64, CIN=64
        int j = i - 294912 - 73728;
        int t  = j % 9;
        int ci = (j / 9) % 64;
        int o  = j / (9 * 64);
        w2[(t * 64 + o) * 64 + ci] = __float2half_rn(c2w[j]);
    } else if (i < 294912 + 73728 + 36864 + 16384) {  // upconv: bf16 hi/lo
        int s = i - 294912 - 73728 - 36864;
        int n = s & 255;
        int cc = s >> 8;
        float v = upw[s];
        __nv_bfloat16 h = __float2bfloat16(v);
        float lo = v - __bfloat162float(h);
        wuh[n * 64 + cc] = h;
        wul[n * 64 + cc] = __float2bfloat16(lo);
    }
}

// ================= x1 NCHW -> NHWC bf16 hi/lo =================
__global__ void __launch_bounds__(256)
tc_x1_k(const float* __restrict__ in0,
        __nv_bfloat16* __restrict__ oh, __nv_bfloat16* __restrict__ ol)
{
    __shared__ float s[64][33];
    const int s0 = blockIdx.x * 32;
    const int b = blockIdx.y;
    const int tid = threadIdx.x;
    const int px = tid & 31;
#pragma unroll 4
    for (int c = tid >> 5; c < 64; c += 8)
        s[c][px] = in0[(b * 64 + c) * 16384 + s0 + px];
    __syncthreads();
#pragma unroll 4
    for (int e = tid; e < 32 * 64; e += 256) {
        int p = e >> 6, c = e & 63;
        float v = s[c][p];
        __nv_bfloat16 h = __float2bfloat16(v);
        float lo = v - __bfloat162float(h);
        size_t idx = ((size_t)(b * 16384 + s0 + p)) * 64 + c;
        oh[idx] = h;
        ol[idx] = __float2bfloat16(lo);
    }
}

// ================= x2 -> NHWC fp16 channels [0:64) of g_cat =================
__global__ void __launch_bounds__(256)
tc_cat_k(const float* __restrict__ x2, __half* __restrict__ oc)
{
    __shared__ float s[64][33];
    const int s0 = blockIdx.x * 32;
    const int b = blockIdx.y;
    const int tid = threadIdx.x;
    const int px = tid & 31;
#pragma unroll 4
    for (int c = tid >> 5; c < 64; c += 8)
        s[c][px] = x2[(b * 64 + c) * HWSZ + s0 + px];
    __syncthreads();
#pragma unroll 4
    for (int e = tid; e < 32 * 64; e += 256) {
        int p = e >> 6, c = e & 63;
        size_t idx = ((size_t)(b * HWSZ + s0 + p)) * 128 + c;
        oc[idx] = __float2half_rn(s[c][p]);
    }
}

// ================= upconv via mma (bf16x3), dual output =================
// Writes g_up (NCHW fp32) AND g_cat channels [64:128) (NHWC fp16).
__global__ void __launch_bounds__(256, 2)
upmma_k(const __nv_bfloat16* __restrict__ ah_g, const __nv_bfloat16* __restrict__ al_g,
        const __nv_bfloat16* __restrict__ bh_g, const __nv_bfloat16* __restrict__ bl_g,
        const float* __restrict__ upb, float* __restrict__ up, __half* __restrict__ cat)
{
    extern __shared__ char dsm[];
    constexpr int A_H = 0, A_L = 16384, B_H = 32768, B_L = 40960;
    uint32_t raw = smem_u32(dsm);
    uint32_t base = (raw + 1023u) & ~1023u;
    char* smc = dsm + (base - raw);
    const int tid = threadIdx.x;
    const int wid = tid >> 5;
    const int lane = tid & 31;

    const int p0 = blockIdx.x * 128;
    const int b  = p0 >> 14;
    const int sb = p0 & 16383;
    const int y0 = sb >> 7;
    const int oc0 = blockIdx.y * 64;

#pragma unroll
    for (int it = 0; it < 4; it++) {
        int idx = it * 256 + tid;
        int m = idx >> 3, ch = idx & 7;
        size_t gi = ((size_t)(p0 + m)) * 64 + ch * 8;
        uint32_t sw = SW128(m * 128 + ch * 16);
        cpa16(base + A_H + sw, ah_g + gi, 16);
        cpa16(base + A_L + sw, al_g + gi, 16);
    }
#pragma unroll
    for (int it = 0; it < 2; it++) {
        int idx = it * 256 + tid;
        int o = idx >> 3, ch = idx & 7;
        size_t gi = ((size_t)(oc0 + o)) * 64 + ch * 8;
        uint32_t sw = SW128(o * 128 + ch * 16);
        cpa16(base + B_H + sw, bh_g + gi, 16);
        cpa16(base + B_L + sw, bl_g + gi, 16);
    }
    cpa_commit();
    cpa_wait<0>();
    __syncthreads();

    float acc[8][4];
#pragma unroll
    for (int g = 0; g < 8; g++)
#pragma unroll
        for (int j = 0; j < 4; j++) acc[g][j] = 0.f;

    const uint32_t Ah = base + A_H, Al = base + A_L;
    const uint32_t Bh = base + B_H, Bl = base + B_L;
    const int arow = wid * 16 + (lane & 15);
    const int nrow = lane & 15;
    const int chalf = (lane >> 4) * 16;
#pragma unroll
    for (int kk = 0; kk < 4; kk++) {
        const int cb = chalf + kk * 32;
        uint32_t ah[4], al[4];
        ldm_x4(ah[0], ah[1], ah[2], ah[3], Ah + SW128(arow * 128 + cb));
        ldm_x4(al[0], al[1], al[2], al[3], Al + SW128(arow * 128 + cb));
#pragma unroll
        for (int g = 0; g < 4; g++) {
            uint32_t off = SW128((g * 16 + nrow) * 128 + cb);
            uint32_t t0, t1, t2, t3, u0, u1, u2, u3;
            ldm_x4(t0, t1, t2, t3, Bh + off);
            ldm_x4(u0, u1, u2, u3, Bl + off);
            mma_bf16(acc[2 * g],     ah, t0, t2);
            mma_bf16(acc[2 * g + 1], ah, t1, t3);
            mma_bf16(acc[2 * g],     al, t0, t2);
            mma_bf16(acc[2 * g + 1], al, t1, t3);
            mma_bf16(acc[2 * g],     ah, u0, u2);
            mma_bf16(acc[2 * g + 1], ah, u1, u3);
        }
    }
    __syncthreads();

    float* sepi = (float*)smc;
    const int em = wid * 16 + (lane >> 2);
    const int en = (lane & 3) * 2;
#pragma unroll
    for (int g = 0; g < 8; g++) {
        int n0 = g * 8 + en;
        sepi[n0 * 132 + em]           = acc[g][0];
        sepi[(n0 + 1) * 132 + em]     = acc[g][1];
        sepi[n0 * 132 + em + 8]       = acc[g][2];
        sepi[(n0 + 1) * 132 + em + 8] = acc[g][3];
    }
    __syncthreads();
    // NCHW fp32 writes
#pragma unroll 4
    for (int j = 0; j < 32; j++) {
        int lin = j * 256 + tid;
        int n = lin >> 7, m = lin & 127;
        int ng = oc0 + n;
        int o = ng >> 2, k = (ng >> 1) & 1, l = ng & 1;
        float v = sepi[n * 132 + m] + upb[o];
        up[((size_t)(b * 64 + o) << 16) + (2 * y0 + k) * 256 + 2 * m + l] = v;
    }
    // NHWC fp16 writes into g_cat channels [64:128): this CTA covers 16 channels
    {
        const int oc00 = oc0 >> 2;             // first output channel (0..48)
#pragma unroll
        for (int it = 0; it < 2; it++) {
            int pi = it * 256 + tid;           // 0..511
            int m = pi >> 2, kl = pi & 3;
            int k = kl >> 1, l = kl & 1;
            float bzv[1];
            unsigned short hs[16];
#pragma unroll
            for (int j = 0; j < 16; j++) {
                float v = sepi[(4 * j + kl) * 132 + m] + upb[oc00 + j];
                __half hb = __float2half_rn(v);
                hs[j] = *(unsigned short*)&hb;
            }
            (void)bzv;
            size_t dst = ((size_t)(b * 65536 + (2 * y0 + k) * 256 + 2 * m + l)) * 128
                         + 64 + oc00;
            uint4* dp = (uint4*)((unsigned short*)cat + dst);
            dp[0] = ((uint4*)hs)[0];
            dp[1] = ((uint4*)hs)[1];
        }
    }
}

// ============ ROW-STAGED implicit-GEMM 3x3 conv (generalized) ============
// EPI 0: NCHW fp32 + bias + stats. EPI 1: NHWC fp32 + bias + stats.
// EPI 2: NCHW fp16 (no bias/stats).
// AFF=1 (CINQ==1): fp32 NHWC input with affine+relu+fp16 on stage.
template<int NTOT, int CINQ, int NT, int EPI, int AFF>
__global__ void __launch_bounds__(512)
convrs_k(const void* __restrict__ a_gv,
         const __half* __restrict__ bh_g,
         const float* __restrict__ aff,
         const float* __restrict__ bias, void* __restrict__ outv,
         float* __restrict__ red)
{
    extern __shared__ char dsm[];
    constexpr int CCH = CINQ * 64;
    constexpr int NW  = NT / 2;
    constexpr int NG  = NW / 16;
    constexpr int A_BYTES = 776 * 128;
    constexpr int B_OFF = A_BYTES;              // 99328
    constexpr int B_BUF = NT * 128;

    uint32_t raw = smem_u32(dsm);
    uint32_t base = (raw + 1023u) & ~1023u;
    char* smc = dsm + (base - raw);
    const int tid = threadIdx.x;
    const int wid = tid >> 5;
    const int lane = tid & 31;
    const int mw = wid & 7;
    const int nw = wid >> 3;

    const int b  = blockIdx.x >> 8;
    const int y0 = blockIdx.x & 255;
    const int sb = y0 << 8;
    const int oc0 = blockIdx.y * NT;

    auto stageA = [&](int q) {
        if (AFF) {
            const float* a32 = (const float*)a_gv;
            for (int idx = tid; idx < 6192; idx += 512) {
                int p = idx >> 3, ch = idx & 7;
                int brow = p / 258;
                int bcol = p - brow * 258;
                int gy = y0 + brow - 1;
                int gx = bcol - 1;
                bool inb = ((unsigned)gy < 256u) && ((unsigned)gx < 256u);
                uint4 pk = make_uint4(0, 0, 0, 0);
                if (inb) {
                    size_t gi = (((size_t)b << 16) + (gy << 8) + gx) * 64 + ch * 8;
                    float4 v0 = *(const float4*)(a32 + gi);
                    float4 v1 = *(const float4*)(a32 + gi + 4);
                    float vv[8] = {v0.x, v0.y, v0.z, v0.w, v1.x, v1.y, v1.z, v1.w};
                    unsigned short hs[8];
#pragma unroll
                    for (int j = 0; j < 8; j++) {
                        int c = ch * 8 + j;
                        float y = fmaxf(fmaf(vv[j], __ldg(aff + c), __ldg(aff + 64 + c)), 0.f);
                        __half hb = __float2half_rn(y);
                        hs[j] = *(unsigned short*)&hb;
                    }
                    pk = *(uint4*)hs;
                }
                *(uint4*)(smc + SW128(p * 128 + ch * 16)) = pk;
            }
        } else {
            const __half* a_g = (const __half*)a_gv;
            for (int idx = tid; idx < 6192; idx += 512) {
                int p = idx >> 3, ch = idx & 7;
                int brow = p / 258;
                int bcol = p - brow * 258;
                int gy = y0 + brow - 1;
                int gx = bcol - 1;
                bool inb = ((unsigned)gy < 256u) && ((unsigned)gx < 256u);
                size_t gi = (((size_t)b << 16) + (gy << 8) + gx) * CCH + q * 64 + ch * 8;
                if (!inb) gi = 0;
                cpa16(base + SW128(p * 128 + ch * 16), a_g + gi, inb ? 16 : 0);
            }
        }
    };
    auto stageB = [&](int kc, int buf) {
        const uint32_t bbase = base + B_OFF + buf * B_BUF;
        for (int idx = tid; idx < NT * 8; idx += 512) {
            int o = idx >> 3, ch = idx & 7;
            size_t gi = ((size_t)kc * NTOT + oc0 + o) * 64 + ch * 8;
            cpa16(bbase + SW128(o * 128 + ch * 16), bh_g + gi, 16);
        }
    };

    float acc[2][NW / 8][4];
#pragma unroll
    for (int ms = 0; ms < 2; ms++)
#pragma unroll
        for (int g = 0; g < NW / 8; g++)
#pragma unroll
            for (int j = 0; j < 4; j++) acc[ms][g][j] = 0.f;

    stageA(0);
    stageB(0, 0);
    cpa_commit();

    const int chalf = (lane >> 4) * 16;
    const int nrow = lane & 15;
    const int arowb = mw * 32 + (lane & 15);

#pragma unroll 1
    for (int q = 0; q < CINQ; q++) {
#pragma unroll 1
        for (int t = 0; t < 9; t++) {
            const int s = q * 9 + t;
            if (t < 8) {
                stageB((t + 1) * CINQ + q, (s + 1) & 1);
                cpa_commit();
                cpa_wait<1>();
            } else {
                cpa_wait<0>();
            }
            __syncthreads();

            const int ky = t / 3 - 1;
            const int kx = t % 3 - 1;
            const uint32_t Bb = base + B_OFF + (s & 1) * B_BUF;
            const int rb = (ky + 1) * 258 + kx + 1 + arowb;

#pragma unroll
            for (int kk = 0; kk < 4; kk++) {
                const int cb = chalf + kk * 32;
                uint32_t ah[2][4];
#pragma unroll
                for (int ms = 0; ms < 2; ms++) {
                    int r = rb + ms * 16;
                    ldm_x4(ah[ms][0], ah[ms][1], ah[ms][2], ah[ms][3],
                           base + SW128(r * 128 + cb));
                }
#pragma unroll
                for (int g = 0; g < NG; g++) {
                    uint32_t off = SW128((nw * NW + g * 16 + nrow) * 128 + cb);
                    uint32_t t0, t1, t2, t3;
                    ldm_x4(t0, t1, t2, t3, Bb + off);
#pragma unroll
                    for (int ms = 0; ms < 2; ms++) {
                        mma_f16(acc[ms][2 * g],     ah[ms], t0, t2);
                        mma_f16(acc[ms][2 * g + 1], ah[ms], t1, t3);
                    }
                }
            }
            __syncthreads();

            if (t == 8 && q + 1 < CINQ) {
                stageA(q + 1);
                stageB(q + 1, (s + 1) & 1);
                cpa_commit();
            }
        }
    }

    // ---- stage [n][m=256] fp32 in smem (pitch 260) ----
    float* sepi = (float*)smc;
    const int em = mw * 32 + (lane >> 2);
    const int ecol = (lane & 3) * 2;
#pragma unroll
    for (int ms = 0; ms < 2; ms++) {
        int m = em + ms * 16;
#pragma unroll
        for (int g = 0; g < NG; g++) {
            int nb = nw * NW + g * 16 + ecol;
            sepi[nb * 260 + m]           = acc[ms][2 * g][0];
            sepi[(nb + 1) * 260 + m]     = acc[ms][2 * g][1];
            sepi[nb * 260 + m + 8]       = acc[ms][2 * g][2];
            sepi[(nb + 1) * 260 + m + 8] = acc[ms][2 * g][3];
            int nb2 = nb + 8;
            sepi[nb2 * 260 + m]           = acc[ms][2 * g + 1][0];
            sepi[(nb2 + 1) * 260 + m]     = acc[ms][2 * g + 1][1];
            sepi[nb2 * 260 + m + 8]       = acc[ms][2 * g + 1][2];
            sepi[(nb2 + 1) * 260 + m + 8] = acc[ms][2 * g + 1][3];
        }
    }
    __syncthreads();

    if (EPI == 0) {
        float* out = (float*)outv;
#pragma unroll
        for (int j = 0; j < NT / 8; j++) {
            int lin = j * 512 + tid;
            int n = lin >> 6;
            int seg = lin & 63;
            float4 v = *(float4*)(sepi + n * 260 + seg * 4);
            float bz = bias ? bias[oc0 + n] : 0.f;
            v.x += bz; v.y += bz; v.z += bz; v.w += bz;
            *(float4*)(out + (((size_t)(b * NTOT + oc0 + n)) << 16) + sb + seg * 4) = v;
        }
    } else if (EPI == 1) {
        float* out = (float*)outv;
#pragma unroll
        for (int j = 0; j < 8; j++) {
            int lin = j * 512 + tid;
            int m = lin >> 4;
            int cq = lin & 15;
            float4 v;
            v.x = sepi[(cq * 4 + 0) * 260 + m] + bias[cq * 4 + 0];
            v.y = sepi[(cq * 4 + 1) * 260 + m] + bias[cq * 4 + 1];
            v.z = sepi[(cq * 4 + 2) * 260 + m] + bias[cq * 4 + 2];
            v.w = sepi[(cq * 4 + 3) * 260 + m] + bias[cq * 4 + 3];
            *(float4*)(out + ((size_t)(b * 65536 + sb + m)) * 64 + cq * 4) = v;
        }
    } else {
        __half* out = (__half*)outv;
#pragma unroll
        for (int j = 0; j < NT / 8; j++) {
            int lin = j * 512 + tid;
            int n = lin >> 6;
            int seg = lin & 63;
            const float* sp = sepi + n * 260 + seg * 4;
            __half h0 = __float2half_rn(sp[0]);
            __half h1 = __float2half_rn(sp[1]);
            __half h2 = __float2half_rn(sp[2]);
            __half h3 = __float2half_rn(sp[3]);
            unsigned short hs[4] = {*(unsigned short*)&h0, *(unsigned short*)&h1,
                                    *(unsigned short*)&h2, *(unsigned short*)&h3};
            *(uint2*)((unsigned short*)out + (((size_t)(b * NTOT + oc0 + n)) << 16)
                      + sb + seg * 4) = *(uint2*)hs;
        }
    }

    if ((EPI == 0 || EPI == 1) && red) {
        float* sred = sepi + NT * 260;
        int n = tid >> 3, part = tid & 7;
        float bz = bias ? bias[oc0 + n] : 0.f;
        float s1 = 0.f, s2 = 0.f;
        const float* rowp = sepi + n * 260 + part * 32;
#pragma unroll
        for (int j = 0; j < 32; j++) {
            float v = rowp[j] + bz;
            s1 += v;
            s2 = fmaf(v, v, s2);
        }
        sred[(0 * 64 + n) * 8 + part] = s1;
        sred[(1 * 64 + n) * 8 + part] = s2;
        __syncthreads();
        if (tid < 128) {
            int which = tid >> 6, n2 = tid & 63;
            const float* pr = sred + (which * 64 + n2) * 8;
            float s = 0.f;
#pragma unroll
            for (int j = 0; j < 8; j++) s += pr[j];
            atomicAdd(red + which * 64 + oc0 + n2, s);
        }
    }
}

// ================= deformable gather (fp16 offsets) -> xd NHWC fp16 =================
__global__ void __launch_bounds__(256)
gathercvt_k(const float* __restrict__ x2, const float* __restrict__ up,
            const __half* __restrict__ offs, __half* __restrict__ oc)
{
    __shared__ float s[128][33];
    const int s0 = blockIdx.x * 32;
    const int b = blockIdx.y;
    const int tid = threadIdx.x;
    const int px = tid & 31;
    const int hw = s0 + px;
    const int h = hw >> 8;
    const int w = hw & 255;
#pragma unroll 4
    for (int c = tid >> 5; c < 128; c += 8) {
        const float* src = (c < 64) ? x2 + (b * 64 + c) * HWSZ
                                    : up + (b * 64 + (c - 64)) * HWSZ;
        int obase = b * C256 * HWSZ + c * 2 * HWSZ + h * (2 * WW) + 2 * w;
        float oy = __half2float(offs[obase]);
        float ox = __half2float(offs[obase + 1]);
        float cy = fminf(fmaxf(oy + (float)h, 0.f), 255.f);
        float cx = fminf(fmaxf(ox + (float)w, 0.f), 255.f);
        float y0f = floorf(cy), x0f = floorf(cx);
        int y0 = (int)y0f;
        int x0 = (int)x0f;
        int y1 = (int)ceilf(cy);
        int x1 = (int)ceilf(cx);
        float v00 = src[y0 * WW + x0];
        float v10 = src[y1 * WW + x0];
        float v01 = src[y0 * WW + x1];
        float v11 = src[y1 * WW + x1];
        float wy = cy - y0f, wx = cx - x0f;
        float vt = v00 + (v10 - v00) * wy;
        float vb = v01 + (v11 - v01) * wy;
        s[c][px] = vt + (vb - vt) * wx;
    }
    __syncthreads();
#pragma unroll 4
    for (int e = tid; e < 32 * 128; e += 256) {
        int p = e >> 7, c = e & 127;
        size_t idx = ((size_t)(b * HWSZ + s0 + p)) * 128 + c;
        oc[idx] = __float2half_rn(s[c][p]);
    }
}

// ================= small kernels =================
__global__ void bnfin_k(const float* __restrict__ red,
                        const float* __restrict__ gamma, const float* __restrict__ beta,
                        float* __restrict__ ab)
{
    int c = threadIdx.x;
    const float invn = 1.f / 131072.f;
    float m = red[c] * invn;
    float var = fmaf(-m, m, red[64 + c] * invn);
    float a = gamma[c] * rsqrtf(var + 1e-5f);
    ab[c] = a;
    ab[64 + c] = fmaf(-m, a, beta[c]);
}

__global__ void __launch_bounds__(256)
bnrelu_out_k(const float* __restrict__ buf, const float* __restrict__ ab,
             float* __restrict__ out)
{
    int i4 = blockIdx.x * 256 + threadIdx.x;
    int c = (i4 >> 14) & 63;
    float a = __ldg(ab + c), bz = __ldg(ab + 64 + c);
    float4 v = *(const float4*)(buf + (size_t)i4 * 4);
    v.x = fmaxf(fmaf(v.x, a, bz), 0.f);
    v.y = fmaxf(fmaf(v.y, a, bz), 0.f);
    v.z = fmaxf(fmaf(v.z, a, bz), 0.f);
    v.w = fmaxf(fmaf(v.w, a, bz), 0.f);
    *(float4*)(out + (size_t)i4 * 4) = v;
}

// ================= launch =================
extern "C" void kernel_launch(void* const* d_in, const int* in_sizes, int n_in,
                              void* d_out, int out_size)
{
    const float* x1   = (const float*)d_in[0];
    const float* x2   = (const float*)d_in[1];
    const float* up_w = (const float*)d_in[2];
    const float* up_b = (const float*)d_in[3];
    const float* offw = (const float*)d_in[4];
    const float* c1w  = (const float*)d_in[5];
    const float* c1b  = (const float*)d_in[6];
    const float* g1   = (const float*)d_in[7];
    const float* b1   = (const float*)d_in[8];
    const float* c2w  = (const float*)d_in[9];
    const float* c2b  = (const float*)d_in[10];
    const float* g2   = (const float*)d_in[11];
    const float* b2   = (const float*)d_in[12];
    float* outp = (float*)d_out;

    float *p_up, *p_h1raw, *p_b2, *p_red, *p_ab1, *p_ab2;
    cudaGetSymbolAddress((void**)&p_up,    g_up);
    cudaGetSymbolAddress((void**)&p_h1raw, g_h1raw);
    cudaGetSymbolAddress((void**)&p_b2,    g_b2);
    cudaGetSymbolAddress((void**)&p_red,   g_red);
    cudaGetSymbolAddress((void**)&p_ab1,   g_ab1);
    cudaGetSymbolAddress((void**)&p_ab2,   g_ab2);
    __nv_bfloat16 *p_x1_h, *p_x1_l, *p_wu_h, *p_wu_l;
    cudaGetSymbolAddress((void**)&p_x1_h, g_x1_h);
    cudaGetSymbolAddress((void**)&p_x1_l, g_x1_l);
    cudaGetSymbolAddress((void**)&p_wu_h, g_wu_h);
    cudaGetSymbolAddress((void**)&p_wu_l, g_wu_l);
    __half *p_off, *p_cat, *p_xd, *p_wo, *p_w1, *p_w2;
    cudaGetSymbolAddress((void**)&p_off, g_off);
    cudaGetSymbolAddress((void**)&p_cat, g_cat);
    cudaGetSymbolAddress((void**)&p_xd,  g_xd);
    cudaGetSymbolAddress((void**)&p_wo,  g_wo);
    cudaGetSymbolAddress((void**)&p_w1,  g_w1);
    cudaGetSymbolAddress((void**)&p_w2,  g_w2);

    const int smem_rs = 135168;
    const int smem_up = 49152 + 1024;
    cudaFuncSetAttribute(convrs_k<256, 2, 128, 2, 0>, cudaFuncAttributeMaxDynamicSharedMemorySize, smem_rs);
    cudaFuncSetAttribute(convrs_k<64, 2, 64, 1, 0>,   cudaFuncAttributeMaxDynamicSharedMemorySize, smem_rs);
    cudaFuncSetAttribute(convrs_k<64, 1, 64, 0, 1>,   cudaFuncAttributeMaxDynamicSharedMemorySize, smem_rs);
    cudaFuncSetAttribute(upmma_k, cudaFuncAttributeMaxDynamicSharedMemorySize, smem_up);

    // 0) combined prep (all weights + zero stats)
    prep_all_k<<<1648, 256>>>(offw, c1w, c2w, up_w, p_wo, p_w1, p_w2,
                              p_wu_h, p_wu_l, p_red);

    // 1) x1 -> NHWC bf16 hi/lo; upconv writes g_up AND g_cat upper channels
    tc_x1_k<<<dim3(512, 2), 256>>>(x1, p_x1_h, p_x1_l);
    upmma_k<<<dim3(256, 4), 256, smem_up>>>(p_x1_h, p_x1_l, p_wu_h, p_wu_l,
                                            up_b, p_up, p_cat);

    // 2) x2 -> g_cat lower channels
    tc_cat_k<<<dim3(2048, 2), 256>>>(x2, p_cat);

    // 3) row-staged offset conv (1-pass) -> g_off fp16 NCHW
    convrs_k<256, 2, 128, 2, 0><<<dim3(512, 2), 512, smem_rs>>>(
        p_cat, p_wo, nullptr, nullptr, p_off, nullptr);

    // 4) gather (fp16 offsets) -> xd NHWC fp16
    gathercvt_k<<<dim3(2048, 2), 256>>>(x2, p_up, p_off, p_xd);

    // 5) row-staged conv1 (1-pass) -> NHWC fp32 + BN1 stats
    convrs_k<64, 2, 64, 1, 0><<<dim3(512, 1), 512, smem_rs>>>(
        p_xd, p_w1, nullptr, c1b, p_h1raw, p_red);
    bnfin_k<<<1, 64>>>(p_red, g1, b1, p_ab1);

    // 6) row-staged conv2 (1-pass, fused BN1 affine+relu) -> NCHW fp32 + BN2 stats
    convrs_k<64, 1, 64, 0, 1><<<dim3(512, 1), 512, smem_rs>>>(
        p_h1raw, p_w2, p_ab1, c2b, p_b2, p_red + 128);
    bnfin_k<<<1, 64>>>(p_red + 128, g2, b2, p_ab2);

    // 7) final BN+ReLU
    bnrelu_out_k<<<8192, 256>>>(p_b2, p_ab2, outp);
}

// round 15
// speedup vs baseline: 1.2665x; 1.0071x over previous
#include <cuda_runtime.h>
#include <cuda_bf16.h>
#include <cuda_fp16.h>
#include <math.h>
#include <stdint.h>

#define HH 256
#define WW 256
#define HWSZ 65536
#define BB 2
#define C64 64
#define C128 128
#define C256 256

#define SW128(off) ((off) ^ (((off) >> 3) & 0x70))

__device__ __forceinline__ uint32_t smem_u32(const void* p) {
    uint32_t a;
    asm("{ .reg .u64 t; cvta.to.shared.u64 t, %1; cvt.u32.u64 %0, t; }" : "=r"(a) : "l"(p));
    return a;
}
__device__ __forceinline__ void cpa16(uint32_t dst, const void* src, int sz) {
    asm volatile("cp.async.cg.shared.global [%0], [%1], 16, %2;"
                 :: "r"(dst), "l"(src), "r"(sz) : "memory");
}
__device__ __forceinline__ void cpa_commit() {
    asm volatile("cp.async.commit_group;" ::: "memory");
}
template<int N>
__device__ __forceinline__ void cpa_wait() {
    asm volatile("cp.async.wait_group %0;" :: "n"(N) : "memory");
}
__device__ __forceinline__ void ldm_x4(uint32_t& r0, uint32_t& r1, uint32_t& r2, uint32_t& r3,
                                       uint32_t addr) {
    asm volatile("ldmatrix.sync.aligned.m8n8.x4.shared.b16 {%0,%1,%2,%3}, [%4];"
                 : "=r"(r0), "=r"(r1), "=r"(r2), "=r"(r3) : "r"(addr));
}
__device__ __forceinline__ void mma_bf16(float* c, const uint32_t* a, uint32_t b0, uint32_t b1) {
    asm volatile("mma.sync.aligned.m16n8k16.row.col.f32.bf16.bf16.f32 "
                 "{%0,%1,%2,%3}, {%4,%5,%6,%7}, {%8,%9}, {%0,%1,%2,%3};"
                 : "+f"(c[0]), "+f"(c[1]), "+f"(c[2]), "+f"(c[3])
                 : "r"(a[0]), "r"(a[1]), "r"(a[2]), "r"(a[3]), "r"(b0), "r"(b1));
}
__device__ __forceinline__ void mma_f16(float* c, const uint32_t* a, uint32_t b0, uint32_t b1) {
    asm volatile("mma.sync.aligned.m16n8k16.row.col.f32.f16.f16.f32 "
                 "{%0,%1,%2,%3}, {%4,%5,%6,%7}, {%8,%9}, {%0,%1,%2,%3};"
                 : "+f"(c[0]), "+f"(c[1]), "+f"(c[2]), "+f"(c[3])
                 : "r"(a[0]), "r"(a[1]), "r"(a[2]), "r"(a[3]), "r"(b0), "r"(b1));
}

// ================= scratch (device globals) =================
__device__ float g_up   [BB * C64 * HWSZ];
__device__ __half g_off [BB * C256 * HWSZ];
__device__ float g_h1raw[BB * HWSZ * C64];
__device__ float g_b2   [BB * C64 * HWSZ];
__device__ float g_red[256];
__device__ __nv_bfloat16 g_x1_h[BB * 16384 * C64];
__device__ __nv_bfloat16 g_x1_l[BB * 16384 * C64];
__device__ __nv_bfloat16 g_wu_h[C256 * 64];
__device__ __nv_bfloat16 g_wu_l[C256 * 64];
__device__ __half g_cat [BB * HWSZ * C128];
__device__ __half g_xd  [BB * HWSZ * C128];
__device__ __half g_wo  [18 * C256 * 64];
__device__ __half g_w1  [18 * C64 * 64];
__device__ __half g_w2  [9 * C64 * 64];

// ================= megaprep: weights + zero stats + x1 split + x2->cat =================
// blocks [0,1648): weight prep + red zero
// blocks [1648,2672): x1 NCHW -> NHWC bf16 hi/lo
// blocks [2672,6768): x2 NCHW -> g_cat NHWC fp16 channels [0:64)
__global__ void __launch_bounds__(256)
megaprep_k(const float* __restrict__ offw, const float* __restrict__ c1w,
           const float* __restrict__ c2w, const float* __restrict__ upw,
           const float* __restrict__ x1, const float* __restrict__ x2,
           __half* __restrict__ wo, __half* __restrict__ w1, __half* __restrict__ w2,
           __nv_bfloat16* __restrict__ wuh, __nv_bfloat16* __restrict__ wul,
           __nv_bfloat16* __restrict__ x1h, __nv_bfloat16* __restrict__ x1l,
           __half* __restrict__ cat, float* __restrict__ red)
{
    __shared__ float s[64][33];
    const int bx = blockIdx.x;
    const int tid = threadIdx.x;

    if (bx < 1648) {
        int i = bx * 256 + tid;
        if (i < 256) red[i] = 0.f;
        if (i < 294912) {                    // offconv weights: N=256, CIN=128
            int t  = i % 9;
            int ci = (i / 9) % 128;
            int o  = i / (9 * 128);
            int q = ci >> 6, cc = ci & 63;
            int kc = t * 2 + q;
            wo[(kc * 256 + o) * 64 + cc] = __float2half_rn(offw[i]);
        } else if (i < 294912 + 73728) {     // conv1: N=64, CIN=128
            int j = i - 294912;
            int t  = j % 9;
            int ci = (j / 9) % 128;
            int o  = j / (9 * 128);
            int q = ci >> 6, cc = ci & 63;
            int kc = t * 2 + q;
            w1[(kc * 64 + o) * 64 + cc] = __float2half_rn(c1w[j]);
        } else if (i < 294912 + 73728 + 36864) {  // conv2: N=64, CIN=64
            int j = i - 294912 - 73728;
            int t  = j % 9;
            int ci = (j / 9) % 64;
            int o  = j / (9 * 64);
            w2[(t * 64 + o) * 64 + ci] = __float2half_rn(c2w[j]);
        } else if (i < 294912 + 73728 + 36864 + 16384) {  // upconv: bf16 hi/lo
            int sdx = i - 294912 - 73728 - 36864;
            int n = sdx & 255;
            int cc = sdx >> 8;
            float v = upw[sdx];
            __nv_bfloat16 h = __float2bfloat16(v);
            float lo = v - __bfloat162float(h);
            wuh[n * 64 + cc] = h;
            wul[n * 64 + cc] = __float2bfloat16(lo);
        }
    } else if (bx < 2672) {
        // x1 transpose-split (b from lin>>9, 512 blocks per batch)
        int lin = bx - 1648;
        int b = lin >> 9;
        int s0 = (lin & 511) * 32;
        const int px = tid & 31;
#pragma unroll 4
        for (int c = tid >> 5; c < 64; c += 8)
            s[c][px] = x1[(b * 64 + c) * 16384 + s0 + px];
        __syncthreads();
#pragma unroll 4
        for (int e = tid; e < 32 * 64; e += 256) {
            int p = e >> 6, c = e & 63;
            float v = s[c][p];
            __nv_bfloat16 h = __float2bfloat16(v);
            float lo = v - __bfloat162float(h);
            size_t idx = ((size_t)(b * 16384 + s0 + p)) * 64 + c;
            x1h[idx] = h;
            x1l[idx] = __float2bfloat16(lo);
        }
    } else {
        // x2 -> g_cat channels [0:64)
        int lin = bx - 2672;
        int b = lin >> 11;
        int s0 = (lin & 2047) * 32;
        const int px = tid & 31;
#pragma unroll 4
        for (int c = tid >> 5; c < 64; c += 8)
            s[c][px] = x2[(b * 64 + c) * HWSZ + s0 + px];
        __syncthreads();
#pragma unroll 4
        for (int e = tid; e < 32 * 64; e += 256) {
            int p = e >> 6, c = e & 63;
            size_t idx = ((size_t)(b * HWSZ + s0 + p)) * 128 + c;
            cat[idx] = __float2half_rn(s[c][p]);
        }
    }
}

// ================= upconv via mma (bf16x3), dual output =================
__global__ void __launch_bounds__(256, 2)
upmma_k(const __nv_bfloat16* __restrict__ ah_g, const __nv_bfloat16* __restrict__ al_g,
        const __nv_bfloat16* __restrict__ bh_g, const __nv_bfloat16* __restrict__ bl_g,
        const float* __restrict__ upb, float* __restrict__ up, __half* __restrict__ cat)
{
    extern __shared__ char dsm[];
    constexpr int A_H = 0, A_L = 16384, B_H = 32768, B_L = 40960;
    uint32_t raw = smem_u32(dsm);
    uint32_t base = (raw + 1023u) & ~1023u;
    char* smc = dsm + (base - raw);
    const int tid = threadIdx.x;
    const int wid = tid >> 5;
    const int lane = tid & 31;

    const int p0 = blockIdx.x * 128;
    const int b  = p0 >> 14;
    const int sb = p0 & 16383;
    const int y0 = sb >> 7;
    const int oc0 = blockIdx.y * 64;

#pragma unroll
    for (int it = 0; it < 4; it++) {
        int idx = it * 256 + tid;
        int m = idx >> 3, ch = idx & 7;
        size_t gi = ((size_t)(p0 + m)) * 64 + ch * 8;
        uint32_t sw = SW128(m * 128 + ch * 16);
        cpa16(base + A_H + sw, ah_g + gi, 16);
        cpa16(base + A_L + sw, al_g + gi, 16);
    }
#pragma unroll
    for (int it = 0; it < 2; it++) {
        int idx = it * 256 + tid;
        int o = idx >> 3, ch = idx & 7;
        size_t gi = ((size_t)(oc0 + o)) * 64 + ch * 8;
        uint32_t sw = SW128(o * 128 + ch * 16);
        cpa16(base + B_H + sw, bh_g + gi, 16);
        cpa16(base + B_L + sw, bl_g + gi, 16);
    }
    cpa_commit();
    cpa_wait<0>();
    __syncthreads();

    float acc[8][4];
#pragma unroll
    for (int g = 0; g < 8; g++)
#pragma unroll
        for (int j = 0; j < 4; j++) acc[g][j] = 0.f;

    const uint32_t Ah = base + A_H, Al = base + A_L;
    const uint32_t Bh = base + B_H, Bl = base + B_L;
    const int arow = wid * 16 + (lane & 15);
    const int nrow = lane & 15;
    const int chalf = (lane >> 4) * 16;
#pragma unroll
    for (int kk = 0; kk < 4; kk++) {
        const int cb = chalf + kk * 32;
        uint32_t ah[4], al[4];
        ldm_x4(ah[0], ah[1], ah[2], ah[3], Ah + SW128(arow * 128 + cb));
        ldm_x4(al[0], al[1], al[2], al[3], Al + SW128(arow * 128 + cb));
#pragma unroll
        for (int g = 0; g < 4; g++) {
            uint32_t off = SW128((g * 16 + nrow) * 128 + cb);
            uint32_t t0, t1, t2, t3, u0, u1, u2, u3;
            ldm_x4(t0, t1, t2, t3, Bh + off);
            ldm_x4(u0, u1, u2, u3, Bl + off);
            mma_bf16(acc[2 * g],     ah, t0, t2);
            mma_bf16(acc[2 * g + 1], ah, t1, t3);
            mma_bf16(acc[2 * g],     al, t0, t2);
            mma_bf16(acc[2 * g + 1], al, t1, t3);
            mma_bf16(acc[2 * g],     ah, u0, u2);
            mma_bf16(acc[2 * g + 1], ah, u1, u3);
        }
    }
    __syncthreads();

    float* sepi = (float*)smc;
    const int em = wid * 16 + (lane >> 2);
    const int en = (lane & 3) * 2;
#pragma unroll
    for (int g = 0; g < 8; g++) {
        int n0 = g * 8 + en;
        sepi[n0 * 132 + em]           = acc[g][0];
        sepi[(n0 + 1) * 132 + em]     = acc[g][1];
        sepi[n0 * 132 + em + 8]       = acc[g][2];
        sepi[(n0 + 1) * 132 + em + 8] = acc[g][3];
    }
    __syncthreads();
    // NCHW fp32 writes
#pragma unroll 4
    for (int j = 0; j < 32; j++) {
        int lin = j * 256 + tid;
        int n = lin >> 7, m = lin & 127;
        int ng = oc0 + n;
        int o = ng >> 2, k = (ng >> 1) & 1, l = ng & 1;
        float v = sepi[n * 132 + m] + upb[o];
        up[((size_t)(b * 64 + o) << 16) + (2 * y0 + k) * 256 + 2 * m + l] = v;
    }
    // NHWC fp16 writes into g_cat channels [64:128)
    {
        const int oc00 = oc0 >> 2;
#pragma unroll
        for (int it = 0; it < 2; it++) {
            int pi = it * 256 + tid;
            int m = pi >> 2, kl = pi & 3;
            int k = kl >> 1, l = kl & 1;
            unsigned short hs[16];
#pragma unroll
            for (int j = 0; j < 16; j++) {
                float v = sepi[(4 * j + kl) * 132 + m] + upb[oc00 + j];
                __half hb = __float2half_rn(v);
                hs[j] = *(unsigned short*)&hb;
            }
            size_t dst = ((size_t)(b * 65536 + (2 * y0 + k) * 256 + 2 * m + l)) * 128
                         + 64 + oc00;
            uint4* dp = (uint4*)((unsigned short*)cat + dst);
            dp[0] = ((uint4*)hs)[0];
            dp[1] = ((uint4*)hs)[1];
        }
    }
}

// ============ ROW-STAGED implicit-GEMM 3x3 conv (generalized) ============
// EPI 0: NCHW fp32 + bias + stats. EPI 1: NHWC fp32 + bias + stats.
// EPI 2: NCHW fp16 (no bias/stats).
// AFF=1 (CINQ==1): fp32 NHWC input; BN affine computed IN-KERNEL from
// (abred, gamma, beta) and applied with relu+fp16 during staging.
template<int NTOT, int CINQ, int NT, int EPI, int AFF>
__global__ void __launch_bounds__(512)
convrs_k(const void* __restrict__ a_gv,
         const __half* __restrict__ bh_g,
         const float* __restrict__ abred, const float* __restrict__ gamma,
         const float* __restrict__ beta,
         const float* __restrict__ bias, void* __restrict__ outv,
         float* __restrict__ red)
{
    extern __shared__ char dsm[];
    __shared__ float s_ab[128];
    constexpr int CCH = CINQ * 64;
    constexpr int NW  = NT / 2;
    constexpr int NG  = NW / 16;
    constexpr int A_BYTES = 776 * 128;
    constexpr int B_OFF = A_BYTES;              // 99328
    constexpr int B_BUF = NT * 128;

    uint32_t raw = smem_u32(dsm);
    uint32_t base = (raw + 1023u) & ~1023u;
    char* smc = dsm + (base - raw);
    const int tid = threadIdx.x;
    const int wid = tid >> 5;
    const int lane = tid & 31;
    const int mw = wid & 7;
    const int nw = wid >> 3;

    const int b  = blockIdx.x >> 8;
    const int y0 = blockIdx.x & 255;
    const int sb = y0 << 8;
    const int oc0 = blockIdx.y * NT;

    if (AFF) {
        if (tid < 64) {
            const float invn = 1.f / 131072.f;
            float m = abred[tid] * invn;
            float var = fmaf(-m, m, abred[64 + tid] * invn);
            float a = gamma[tid] * rsqrtf(var + 1e-5f);
            s_ab[tid] = a;
            s_ab[64 + tid] = fmaf(-m, a, beta[tid]);
        }
        __syncthreads();
    }

    auto stageA = [&](int q) {
        if (AFF) {
            const float* a32 = (const float*)a_gv;
            for (int idx = tid; idx < 6192; idx += 512) {
                int p = idx >> 3, ch = idx & 7;
                int brow = p / 258;
                int bcol = p - brow * 258;
                int gy = y0 + brow - 1;
                int gx = bcol - 1;
                bool inb = ((unsigned)gy < 256u) && ((unsigned)gx < 256u);
                uint4 pk = make_uint4(0, 0, 0, 0);
                if (inb) {
                    size_t gi = (((size_t)b << 16) + (gy << 8) + gx) * 64 + ch * 8;
                    float4 v0 = *(const float4*)(a32 + gi);
                    float4 v1 = *(const float4*)(a32 + gi + 4);
                    float vv[8] = {v0.x, v0.y, v0.z, v0.w, v1.x, v1.y, v1.z, v1.w};
                    unsigned short hs[8];
#pragma unroll
                    for (int j = 0; j < 8; j++) {
                        int c = ch * 8 + j;
                        float y = fmaxf(fmaf(vv[j], s_ab[c], s_ab[64 + c]), 0.f);
                        __half hb = __float2half_rn(y);
                        hs[j] = *(unsigned short*)&hb;
                    }
                    pk = *(uint4*)hs;
                }
                *(uint4*)(smc + SW128(p * 128 + ch * 16)) = pk;
            }
        } else {
            const __half* a_g = (const __half*)a_gv;
            for (int idx = tid; idx < 6192; idx += 512) {
                int p = idx >> 3, ch = idx & 7;
                int brow = p / 258;
                int bcol = p - brow * 258;
                int gy = y0 + brow - 1;
                int gx = bcol - 1;
                bool inb = ((unsigned)gy < 256u) && ((unsigned)gx < 256u);
                size_t gi = (((size_t)b << 16) + (gy << 8) + gx) * CCH + q * 64 + ch * 8;
                if (!inb) gi = 0;
                cpa16(base + SW128(p * 128 + ch * 16), a_g + gi, inb ? 16 : 0);
            }
        }
    };
    auto stageB = [&](int kc, int buf) {
        const uint32_t bbase = base + B_OFF + buf * B_BUF;
        for (int idx = tid; idx < NT * 8; idx += 512) {
            int o = idx >> 3, ch = idx & 7;
            size_t gi = ((size_t)kc * NTOT + oc0 + o) * 64 + ch * 8;
            cpa16(bbase + SW128(o * 128 + ch * 16), bh_g + gi, 16);
        }
    };

    float acc[2][NW / 8][4];
#pragma unroll
    for (int ms = 0; ms < 2; ms++)
#pragma unroll
        for (int g = 0; g < NW / 8; g++)
#pragma unroll
            for (int j = 0; j < 4; j++) acc[ms][g][j] = 0.f;

    stageA(0);
    stageB(0, 0);
    cpa_commit();

    const int chalf = (lane >> 4) * 16;
    const int nrow = lane & 15;
    const int arowb = mw * 32 + (lane & 15);

#pragma unroll 1
    for (int q = 0; q < CINQ; q++) {
#pragma unroll 1
        for (int t = 0; t < 9; t++) {
            const int s = q * 9 + t;
            if (t < 8) {
                stageB((t + 1) * CINQ + q, (s + 1) & 1);
                cpa_commit();
                cpa_wait<1>();
            } else {
                cpa_wait<0>();
            }
            __syncthreads();

            const int ky = t / 3 - 1;
            const int kx = t % 3 - 1;
            const uint32_t Bb = base + B_OFF + (s & 1) * B_BUF;
            const int rb = (ky + 1) * 258 + kx + 1 + arowb;

#pragma unroll
            for (int kk = 0; kk < 4; kk++) {
                const int cb = chalf + kk * 32;
                uint32_t ah[2][4];
#pragma unroll
                for (int ms = 0; ms < 2; ms++) {
                    int r = rb + ms * 16;
                    ldm_x4(ah[ms][0], ah[ms][1], ah[ms][2], ah[ms][3],
                           base + SW128(r * 128 + cb));
                }
#pragma unroll
                for (int g = 0; g < NG; g++) {
                    uint32_t off = SW128((nw * NW + g * 16 + nrow) * 128 + cb);
                    uint32_t t0, t1, t2, t3;
                    ldm_x4(t0, t1, t2, t3, Bb + off);
#pragma unroll
                    for (int ms = 0; ms < 2; ms++) {
                        mma_f16(acc[ms][2 * g],     ah[ms], t0, t2);
                        mma_f16(acc[ms][2 * g + 1], ah[ms], t1, t3);
                    }
                }
            }
            __syncthreads();

            if (t == 8 && q + 1 < CINQ) {
                stageA(q + 1);
                stageB(q + 1, (s + 1) & 1);
                cpa_commit();
            }
        }
    }

    // ---- stage [n][m=256] fp32 in smem (pitch 260) ----
    float* sepi = (float*)smc;
    const int em = mw * 32 + (lane >> 2);
    const int ecol = (lane & 3) * 2;
#pragma unroll
    for (int ms = 0; ms < 2; ms++) {
        int m = em + ms * 16;
#pragma unroll
        for (int g = 0; g < NG; g++) {
            int nb = nw * NW + g * 16 + ecol;
            sepi[nb * 260 + m]           = acc[ms][2 * g][0];
            sepi[(nb + 1) * 260 + m]     = acc[ms][2 * g][1];
            sepi[nb * 260 + m + 8]       = acc[ms][2 * g][2];
            sepi[(nb + 1) * 260 + m + 8] = acc[ms][2 * g][3];
            int nb2 = nb + 8;
            sepi[nb2 * 260 + m]           = acc[ms][2 * g + 1][0];
            sepi[(nb2 + 1) * 260 + m]     = acc[ms][2 * g + 1][1];
            sepi[nb2 * 260 + m + 8]       = acc[ms][2 * g + 1][2];
            sepi[(nb2 + 1) * 260 + m + 8] = acc[ms][2 * g + 1][3];
        }
    }
    __syncthreads();

    if (EPI == 0) {
        float* out = (float*)outv;
#pragma unroll
        for (int j = 0; j < NT / 8; j++) {
            int lin = j * 512 + tid;
            int n = lin >> 6;
            int seg = lin & 63;
            float4 v = *(float4*)(sepi + n * 260 + seg * 4);
            float bz = bias ? bias[oc0 + n] : 0.f;
            v.x += bz; v.y += bz; v.z += bz; v.w += bz;
            *(float4*)(out + (((size_t)(b * NTOT + oc0 + n)) << 16) + sb + seg * 4) = v;
        }
    } else if (EPI == 1) {
        float* out = (float*)outv;
#pragma unroll
        for (int j = 0; j < 8; j++) {
            int lin = j * 512 + tid;
            int m = lin >> 4;
            int cq = lin & 15;
            float4 v;
            v.x = sepi[(cq * 4 + 0) * 260 + m] + bias[cq * 4 + 0];
            v.y = sepi[(cq * 4 + 1) * 260 + m] + bias[cq * 4 + 1];
            v.z = sepi[(cq * 4 + 2) * 260 + m] + bias[cq * 4 + 2];
            v.w = sepi[(cq * 4 + 3) * 260 + m] + bias[cq * 4 + 3];
            *(float4*)(out + ((size_t)(b * 65536 + sb + m)) * 64 + cq * 4) = v;
        }
    } else {
        __half* out = (__half*)outv;
#pragma unroll
        for (int j = 0; j < NT / 8; j++) {
            int lin = j * 512 + tid;
            int n = lin >> 6;
            int seg = lin & 63;
            const float* sp = sepi + n * 260 + seg * 4;
            __half h0 = __float2half_rn(sp[0]);
            __half h1 = __float2half_rn(sp[1]);
            __half h2 = __float2half_rn(sp[2]);
            __half h3 = __float2half_rn(sp[3]);
            unsigned short hs[4] = {*(unsigned short*)&h0, *(unsigned short*)&h1,
                                    *(unsigned short*)&h2, *(unsigned short*)&h3};
            *(uint2*)((unsigned short*)out + (((size_t)(b * NTOT + oc0 + n)) << 16)
                      + sb + seg * 4) = *(uint2*)hs;
        }
    }

    if ((EPI == 0 || EPI == 1) && red) {
        float* sred = sepi + NT * 260;
        int n = tid >> 3, part = tid & 7;
        float bz = bias ? bias[oc0 + n] : 0.f;
        float s1 = 0.f, s2 = 0.f;
        const float* rowp = sepi + n * 260 + part * 32;
#pragma unroll
        for (int j = 0; j < 32; j++) {
            float v = rowp[j] + bz;
            s1 += v;
            s2 = fmaf(v, v, s2);
        }
        sred[(0 * 64 + n) * 8 + part] = s1;
        sred[(1 * 64 + n) * 8 + part] = s2;
        __syncthreads();
        if (tid < 128) {
            int which = tid >> 6, n2 = tid & 63;
            const float* pr = sred + (which * 64 + n2) * 8;
            float s = 0.f;
#pragma unroll
            for (int j = 0; j < 8; j++) s += pr[j];
            atomicAdd(red + which * 64 + oc0 + n2, s);
        }
    }
}

// ================= deformable gather (fp16 offsets) -> xd NHWC fp16 =================
__global__ void __launch_bounds__(256)
gathercvt_k(const float* __restrict__ x2, const float* __restrict__ up,
            const __half* __restrict__ offs, __half* __restrict__ oc)
{
    __shared__ float s[128][33];
    const int s0 = blockIdx.x * 32;
    const int b = blockIdx.y;
    const int tid = threadIdx.x;
    const int px = tid & 31;
    const int hw = s0 + px;
    const int h = hw >> 8;
    const int w = hw & 255;
#pragma unroll 4
    for (int c = tid >> 5; c < 128; c += 8) {
        const float* src = (c < 64) ? x2 + (b * 64 + c) * HWSZ
                                    : up + (b * 64 + (c - 64)) * HWSZ;
        int obase = b * C256 * HWSZ + c * 2 * HWSZ + h * (2 * WW) + 2 * w;
        float oy = __half2float(offs[obase]);
        float ox = __half2float(offs[obase + 1]);
        float cy = fminf(fmaxf(oy + (float)h, 0.f), 255.f);
        float cx = fminf(fmaxf(ox + (float)w, 0.f), 255.f);
        float y0f = floorf(cy), x0f = floorf(cx);
        int y0 = (int)y0f;
        int x0 = (int)x0f;
        int y1 = (int)ceilf(cy);
        int x1 = (int)ceilf(cx);
        float v00 = src[y0 * WW + x0];
        float v10 = src[y1 * WW + x0];
        float v01 = src[y0 * WW + x1];
        float v11 = src[y1 * WW + x1];
        float wy = cy - y0f, wx = cx - x0f;
        float vt = v00 + (v10 - v00) * wy;
        float vb = v01 + (v11 - v01) * wy;
        s[c][px] = vt + (vb - vt) * wx;
    }
    __syncthreads();
#pragma unroll 4
    for (int e = tid; e < 32 * 128; e += 256) {
        int p = e >> 7, c = e & 127;
        size_t idx = ((size_t)(b * HWSZ + s0 + p)) * 128 + c;
        oc[idx] = __float2half_rn(s[c][p]);
    }
}

// ================= final BN+ReLU (computes ab2 in-kernel) =================
__global__ void __launch_bounds__(256)
bnrelu_out_k(const float* __restrict__ buf, const float* __restrict__ red,
             const float* __restrict__ gamma, const float* __restrict__ beta,
             float* __restrict__ out)
{
    __shared__ float s_ab[128];
    if (threadIdx.x < 64) {
        int c = threadIdx.x;
        const float invn = 1.f / 131072.f;
        float m = red[c] * invn;
        float var = fmaf(-m, m, red[64 + c] * invn);
        float a = gamma[c] * rsqrtf(var + 1e-5f);
        s_ab[c] = a;
        s_ab[64 + c] = fmaf(-m, a, beta[c]);
    }
    __syncthreads();
    int i4 = blockIdx.x * 256 + threadIdx.x;
    int c = (i4 >> 14) & 63;
    float a = s_ab[c], bz = s_ab[64 + c];
    float4 v = *(const float4*)(buf + (size_t)i4 * 4);
    v.x = fmaxf(fmaf(v.x, a, bz), 0.f);
    v.y = fmaxf(fmaf(v.y, a, bz), 0.f);
    v.z = fmaxf(fmaf(v.z, a, bz), 0.f);
    v.w = fmaxf(fmaf(v.w, a, bz), 0.f);
    *(float4*)(out + (size_t)i4 * 4) = v;
}

// ================= launch =================
extern "C" void kernel_launch(void* const* d_in, const int* in_sizes, int n_in,
                              void* d_out, int out_size)
{
    const float* x1   = (const float*)d_in[0];
    const float* x2   = (const float*)d_in[1];
    const float* up_w = (const float*)d_in[2];
    const float* up_b = (const float*)d_in[3];
    const float* offw = (const float*)d_in[4];
    const float* c1w  = (const float*)d_in[5];
    const float* c1b  = (const float*)d_in[6];
    const float* g1   = (const float*)d_in[7];
    const float* b1   = (const float*)d_in[8];
    const float* c2w  = (const float*)d_in[9];
    const float* c2b  = (const float*)d_in[10];
    const float* g2   = (const float*)d_in[11];
    const float* b2   = (const float*)d_in[12];
    float* outp = (float*)d_out;

    float *p_up, *p_h1raw, *p_b2, *p_red;
    cudaGetSymbolAddress((void**)&p_up,    g_up);
    cudaGetSymbolAddress((void**)&p_h1raw, g_h1raw);
    cudaGetSymbolAddress((void**)&p_b2,    g_b2);
    cudaGetSymbolAddress((void**)&p_red,   g_red);
    __nv_bfloat16 *p_x1_h, *p_x1_l, *p_wu_h, *p_wu_l;
    cudaGetSymbolAddress((void**)&p_x1_h, g_x1_h);
    cudaGetSymbolAddress((void**)&p_x1_l, g_x1_l);
    cudaGetSymbolAddress((void**)&p_wu_h, g_wu_h);
    cudaGetSymbolAddress((void**)&p_wu_l, g_wu_l);
    __half *p_off, *p_cat, *p_xd, *p_wo, *p_w1, *p_w2;
    cudaGetSymbolAddress((void**)&p_off, g_off);
    cudaGetSymbolAddress((void**)&p_cat, g_cat);
    cudaGetSymbolAddress((void**)&p_xd,  g_xd);
    cudaGetSymbolAddress((void**)&p_wo,  g_wo);
    cudaGetSymbolAddress((void**)&p_w1,  g_w1);
    cudaGetSymbolAddress((void**)&p_w2,  g_w2);

    const int smem_rs = 135168;
    const int smem_up = 49152 + 1024;
    cudaFuncSetAttribute(convrs_k<256, 2, 128, 2, 0>, cudaFuncAttributeMaxDynamicSharedMemorySize, smem_rs);
    cudaFuncSetAttribute(convrs_k<64, 2, 64, 1, 0>,   cudaFuncAttributeMaxDynamicSharedMemorySize, smem_rs);
    cudaFuncSetAttribute(convrs_k<64, 1, 64, 0, 1>,   cudaFuncAttributeMaxDynamicSharedMemorySize, smem_rs);
    cudaFuncSetAttribute(upmma_k, cudaFuncAttributeMaxDynamicSharedMemorySize, smem_up);

    // 0) megaprep: weights + red zero + x1 split + x2 -> cat lower channels
    megaprep_k<<<6768, 256>>>(offw, c1w, c2w, up_w, x1, x2,
                              p_wo, p_w1, p_w2, p_wu_h, p_wu_l,
                              p_x1_h, p_x1_l, p_cat, p_red);

    // 1) upconv: writes g_up AND g_cat upper channels
    upmma_k<<<dim3(256, 4), 256, smem_up>>>(p_x1_h, p_x1_l, p_wu_h, p_wu_l,
                                            up_b, p_up, p_cat);

    // 2) row-staged offset conv (1-pass) -> g_off fp16 NCHW
    convrs_k<256, 2, 128, 2, 0><<<dim3(512, 2), 512, smem_rs>>>(
        p_cat, p_wo, nullptr, nullptr, nullptr, nullptr, p_off, nullptr);

    // 3) gather (fp16 offsets) -> xd NHWC fp16
    gathercvt_k<<<dim3(2048, 2), 256>>>(x2, p_up, p_off, p_xd);

    // 4) row-staged conv1 (1-pass) -> NHWC fp32 + BN1 stats
    convrs_k<64, 2, 64, 1, 0><<<dim3(512, 1), 512, smem_rs>>>(
        p_xd, p_w1, nullptr, nullptr, nullptr, c1b, p_h1raw, p_red);

    // 5) row-staged conv2 (1-pass, in-kernel BN1 affine+relu) -> NCHW fp32 + BN2 stats
    convrs_k<64, 1, 64, 0, 1><<<dim3(512, 1), 512, smem_rs>>>(
        p_h1raw, p_w2, p_red, g1, b1, c2b, p_b2, p_red + 128);

    // 6) final BN+ReLU (in-kernel ab2)
    bnrelu_out_k<<<8192, 256>>>(p_b2, p_red + 128, g2, b2, outp);
}